// round 1
// baseline (speedup 1.0000x reference)
#include <cuda_runtime.h>
#include <math.h>

// Problem constants
static constexpr int B  = 8;
static constexpr int S  = 1024;
static constexpr int D  = 1024;
static constexpr int H  = 16;
static constexpr int DK = 64;
static constexpr int M  = B * S;        // 8192 rows for dense GEMMs

static constexpr size_t YSIZE    = (size_t)B * S * D;         // 8,388,608
static constexpr size_t ATTNSIZE = (size_t)B * H * S * S;     // 134,217,728

// Scratch (static device allocations are allowed)
__device__ float g_Q[YSIZE];
__device__ float g_K[YSIZE];
__device__ float g_V[YSIZE];
__device__ float g_ctx[YSIZE];
__device__ float g_x[YSIZE];
__device__ float g_attn[ATTNSIZE];   // fallback if d_out only holds y

// ---------------------------------------------------------------------------
// Dense GEMM: C[M,N] = A[M,K] @ W[N,K]^T + bias[N] (+ res[M,N] if non-null)
// BM=128, BN=64, BK=16, 256 threads, 8x4 per-thread microtile.
// Assumes M%128==0, N%64==0, K%16==0 (true here: 8192/1024/1024).
// ---------------------------------------------------------------------------
__global__ __launch_bounds__(256) void gemm_nt_kernel(
    const float* __restrict__ A, const float* __restrict__ W,
    const float* __restrict__ bias, const float* __restrict__ res,
    float* __restrict__ C, int Mm, int Nn, int Kk)
{
    constexpr int BM = 128, BN = 64, BK = 16, TM = 8, TN = 4;
    __shared__ float As[BK][BM + 4];
    __shared__ float Ws[BK][BN + 4];

    const int tid = threadIdx.x;
    const int block_m = blockIdx.y * BM;
    const int block_n = blockIdx.x * BN;
    const int tx = tid % (BN / TN);   // 0..15 (n)
    const int ty = tid / (BN / TN);   // 0..15 (m)

    float acc[TM][TN];
#pragma unroll
    for (int i = 0; i < TM; i++)
#pragma unroll
        for (int j = 0; j < TN; j++) acc[i][j] = 0.f;

    for (int k0 = 0; k0 < Kk; k0 += BK) {
        // Load A tile: 128x16 = 512 float4, 2 per thread
#pragma unroll
        for (int i = 0; i < 2; i++) {
            int idx = tid + i * 256;
            int m  = idx >> 2;
            int k4 = idx & 3;
            float4 v = *(const float4*)&A[(size_t)(block_m + m) * Kk + k0 + k4 * 4];
            As[k4 * 4 + 0][m] = v.x;
            As[k4 * 4 + 1][m] = v.y;
            As[k4 * 4 + 2][m] = v.z;
            As[k4 * 4 + 3][m] = v.w;
        }
        // Load W tile: 64x16 = 256 float4, 1 per thread
        {
            int n  = tid >> 2;
            int k4 = tid & 3;
            float4 v = *(const float4*)&W[(size_t)(block_n + n) * Kk + k0 + k4 * 4];
            Ws[k4 * 4 + 0][n] = v.x;
            Ws[k4 * 4 + 1][n] = v.y;
            Ws[k4 * 4 + 2][n] = v.z;
            Ws[k4 * 4 + 3][n] = v.w;
        }
        __syncthreads();

#pragma unroll
        for (int k = 0; k < BK; k++) {
            float rm[TM], rn[TN];
#pragma unroll
            for (int i = 0; i < TM; i++) rm[i] = As[k][ty * TM + i];
#pragma unroll
            for (int j = 0; j < TN; j++) rn[j] = Ws[k][tx * TN + j];
#pragma unroll
            for (int i = 0; i < TM; i++)
#pragma unroll
                for (int j = 0; j < TN; j++) acc[i][j] = fmaf(rm[i], rn[j], acc[i][j]);
        }
        __syncthreads();
    }

#pragma unroll
    for (int i = 0; i < TM; i++) {
        int m = block_m + ty * TM + i;
#pragma unroll
        for (int j = 0; j < TN; j++) {
            int n = block_n + tx * TN + j;
            float v = acc[i][j] + bias[n];
            if (res) v += res[(size_t)m * Nn + n];
            C[(size_t)m * Nn + n] = v;
        }
    }
}

// ---------------------------------------------------------------------------
// Scores: scores[bh, q, k] = (Q_head[q,:] . K_head[k,:]) / 8, masked (k<=q)
// One 64x64 tile per block; skip strictly-upper tiles (causal).
// ---------------------------------------------------------------------------
__global__ __launch_bounds__(256) void scores_kernel(
    const float* __restrict__ Q, const float* __restrict__ Kp,
    float* __restrict__ attnbuf)
{
    const int kt = blockIdx.x;
    const int qt = blockIdx.y;
    if (kt > qt) return;
    const int bh = blockIdx.z;
    const int b = bh / H, h = bh % H;

    __shared__ float Qs[64][65];
    __shared__ float Ks[64][65];

    const float* Qbase = Q + (size_t)b * S * D + h * DK;
    const float* Kbase = Kp + (size_t)b * S * D + h * DK;
    const int q0 = qt * 64, k0 = kt * 64;
    const int tid = threadIdx.x;

    // 64 rows x 64 dk = 1024 float4 per operand, 4 per thread
#pragma unroll
    for (int i = 0; i < 4; i++) {
        int idx = tid + i * 256;
        int r = idx >> 4;
        int c4 = idx & 15;
        float4 v = *(const float4*)&Qbase[(size_t)(q0 + r) * D + c4 * 4];
        Qs[r][c4 * 4 + 0] = v.x; Qs[r][c4 * 4 + 1] = v.y;
        Qs[r][c4 * 4 + 2] = v.z; Qs[r][c4 * 4 + 3] = v.w;
        float4 w = *(const float4*)&Kbase[(size_t)(k0 + r) * D + c4 * 4];
        Ks[r][c4 * 4 + 0] = w.x; Ks[r][c4 * 4 + 1] = w.y;
        Ks[r][c4 * 4 + 2] = w.z; Ks[r][c4 * 4 + 3] = w.w;
    }
    __syncthreads();

    const int tx = tid % 16, ty = tid / 16;
    float acc[4][4];
#pragma unroll
    for (int i = 0; i < 4; i++)
#pragma unroll
        for (int j = 0; j < 4; j++) acc[i][j] = 0.f;

#pragma unroll
    for (int k = 0; k < 64; k++) {
        float rq[4], rk[4];
#pragma unroll
        for (int i = 0; i < 4; i++) rq[i] = Qs[ty * 4 + i][k];
#pragma unroll
        for (int j = 0; j < 4; j++) rk[j] = Ks[tx * 4 + j][k];
#pragma unroll
        for (int i = 0; i < 4; i++)
#pragma unroll
            for (int j = 0; j < 4; j++) acc[i][j] = fmaf(rq[i], rk[j], acc[i][j]);
    }

    float* out = attnbuf + (size_t)bh * S * S;
#pragma unroll
    for (int i = 0; i < 4; i++) {
        int q = q0 + ty * 4 + i;
#pragma unroll
        for (int j = 0; j < 4; j++) {
            int kk = k0 + tx * 4 + j;
            float v = (kk <= q) ? acc[i][j] * 0.125f : -1e9f;
            out[(size_t)q * S + kk] = v;
        }
    }
}

// ---------------------------------------------------------------------------
// In-place causal softmax over each row; zero-fill k > q.
// grid = B*H*S blocks, 128 threads.
// ---------------------------------------------------------------------------
__global__ __launch_bounds__(128) void softmax_kernel(float* __restrict__ attnbuf)
{
    const size_t row = blockIdx.x;
    const int q = (int)(row % S);
    float* ptr = attnbuf + row * (size_t)S;
    const int len = q + 1;
    const int tid = threadIdx.x;

    __shared__ float red[128];

    float m = -1e30f;
    for (int i = tid; i < len; i += 128) m = fmaxf(m, ptr[i]);
    red[tid] = m;
    __syncthreads();
#pragma unroll
    for (int s = 64; s > 0; s >>= 1) {
        if (tid < s) red[tid] = fmaxf(red[tid], red[tid + s]);
        __syncthreads();
    }
    m = red[0];
    __syncthreads();

    float sum = 0.f;
    for (int i = tid; i < len; i += 128) {
        float e = __expf(ptr[i] - m);
        ptr[i] = e;
        sum += e;
    }
    red[tid] = sum;
    __syncthreads();
#pragma unroll
    for (int s = 64; s > 0; s >>= 1) {
        if (tid < s) red[tid] += red[tid + s];
        __syncthreads();
    }
    const float inv = 1.f / red[0];
    __syncthreads();

    for (int i = tid; i < len; i += 128) ptr[i] *= inv;
    for (int i = len + tid; i < S; i += 128) ptr[i] = 0.f;
}

// ---------------------------------------------------------------------------
// ctx[b, q, h*DK+dk] = sum_k attn[bh,q,k] * V_head[k,dk]; skip k-tiles > q-tile
// ---------------------------------------------------------------------------
__global__ __launch_bounds__(256) void ctx_kernel(
    const float* __restrict__ attnbuf, const float* __restrict__ V,
    float* __restrict__ ctx)
{
    const int qt = blockIdx.x;
    const int bh = blockIdx.y;
    const int b = bh / H, h = bh % H;

    __shared__ float As[64][65];  // attn [q][k]
    __shared__ float Vs[64][65];  // V    [k][dk]

    const float* arow  = attnbuf + (size_t)bh * S * S;
    const float* Vbase = V + (size_t)b * S * D + h * DK;
    const int q0 = qt * 64;
    const int tid = threadIdx.x;
    const int tx = tid % 16, ty = tid / 16;

    float acc[4][4];
#pragma unroll
    for (int i = 0; i < 4; i++)
#pragma unroll
        for (int j = 0; j < 4; j++) acc[i][j] = 0.f;

    for (int kt = 0; kt <= qt; kt++) {
        const int k0 = kt * 64;
#pragma unroll
        for (int i = 0; i < 4; i++) {
            int idx = tid + i * 256;
            int r = idx >> 4;
            int c4 = idx & 15;
            float4 a = *(const float4*)&arow[(size_t)(q0 + r) * S + k0 + c4 * 4];
            As[r][c4 * 4 + 0] = a.x; As[r][c4 * 4 + 1] = a.y;
            As[r][c4 * 4 + 2] = a.z; As[r][c4 * 4 + 3] = a.w;
            float4 v = *(const float4*)&Vbase[(size_t)(k0 + r) * D + c4 * 4];
            Vs[r][c4 * 4 + 0] = v.x; Vs[r][c4 * 4 + 1] = v.y;
            Vs[r][c4 * 4 + 2] = v.z; Vs[r][c4 * 4 + 3] = v.w;
        }
        __syncthreads();

#pragma unroll
        for (int k = 0; k < 64; k++) {
            float ra[4], rv[4];
#pragma unroll
            for (int i = 0; i < 4; i++) ra[i] = As[ty * 4 + i][k];
#pragma unroll
            for (int j = 0; j < 4; j++) rv[j] = Vs[k][tx * 4 + j];
#pragma unroll
            for (int i = 0; i < 4; i++)
#pragma unroll
                for (int j = 0; j < 4; j++) acc[i][j] = fmaf(ra[i], rv[j], acc[i][j]);
        }
        __syncthreads();
    }

#pragma unroll
    for (int i = 0; i < 4; i++) {
        int q = q0 + ty * 4 + i;
#pragma unroll
        for (int j = 0; j < 4; j++) {
            int dk = tx * 4 + j;
            ctx[(size_t)(b * S + q) * D + h * DK + dk] = acc[i][j];
        }
    }
}

// ---------------------------------------------------------------------------
// Row LayerNorm: y = (x - mu) * rsqrt(var + eps) * gamma + beta
// ---------------------------------------------------------------------------
__global__ __launch_bounds__(256) void ln_kernel(
    const float* __restrict__ x, const float* __restrict__ gamma,
    const float* __restrict__ beta, float* __restrict__ y)
{
    const size_t row = blockIdx.x;
    const float* xr = x + row * (size_t)D;
    float* yr = y + row * (size_t)D;
    const int tid = threadIdx.x;

    __shared__ float rs[256], rs2[256];

    float s = 0.f, s2 = 0.f;
#pragma unroll
    for (int i = 0; i < 4; i++) {
        float v = xr[tid + i * 256];
        s += v;
        s2 += v * v;
    }
    rs[tid] = s; rs2[tid] = s2;
    __syncthreads();
#pragma unroll
    for (int k = 128; k > 0; k >>= 1) {
        if (tid < k) { rs[tid] += rs[tid + k]; rs2[tid] += rs2[tid + k]; }
        __syncthreads();
    }
    const float mean = rs[0] * (1.f / D);
    const float var  = rs2[0] * (1.f / D) - mean * mean;
    const float rstd = rsqrtf(var + 1e-5f);

#pragma unroll
    for (int i = 0; i < 4; i++) {
        int c = tid + i * 256;
        yr[c] = (xr[c] - mean) * rstd * gamma[c] + beta[c];
    }
}

// ---------------------------------------------------------------------------
// Launch
// Inputs: 0 query, 1 key, 2 value, 3 causal_mask(unused), 4 wq, 5 bq,
//         6 wk, 7 bk, 8 wv, 9 bv, 10 wo, 11 bo, 12 gamma, 13 beta
// Output: y [B,S,D] (+ attn [B,H,S,S] if out_size covers it)
// ---------------------------------------------------------------------------
extern "C" void kernel_launch(void* const* d_in, const int* in_sizes, int n_in,
                              void* d_out, int out_size)
{
    const float* query = (const float*)d_in[0];
    const float* key   = (const float*)d_in[1];
    const float* value = (const float*)d_in[2];
    const float* wq = (const float*)d_in[4];
    const float* bq = (const float*)d_in[5];
    const float* wk = (const float*)d_in[6];
    const float* bk = (const float*)d_in[7];
    const float* wv = (const float*)d_in[8];
    const float* bv = (const float*)d_in[9];
    const float* wo = (const float*)d_in[10];
    const float* bo = (const float*)d_in[11];
    const float* gamma = (const float*)d_in[12];
    const float* beta  = (const float*)d_in[13];

    float* y = (float*)d_out;

    // Resolve scratch pointers
    float *Qp, *Kp, *Vp, *ctxp, *xp, *attnp;
    cudaGetSymbolAddress((void**)&Qp,   g_Q);
    cudaGetSymbolAddress((void**)&Kp,   g_K);
    cudaGetSymbolAddress((void**)&Vp,   g_V);
    cudaGetSymbolAddress((void**)&ctxp, g_ctx);
    cudaGetSymbolAddress((void**)&xp,   g_x);
    cudaGetSymbolAddress((void**)&attnp, g_attn);

    float* attnbuf = ((size_t)out_size >= YSIZE + ATTNSIZE) ? (y + YSIZE) : attnp;

    const dim3 gemm_grid(1024 / 64, M / 128);   // (16, 64)

    gemm_nt_kernel<<<gemm_grid, 256>>>(query, wq, bq, nullptr, Qp, M, D, D);
    gemm_nt_kernel<<<gemm_grid, 256>>>(key,   wk, bk, nullptr, Kp, M, D, D);
    gemm_nt_kernel<<<gemm_grid, 256>>>(value, wv, bv, nullptr, Vp, M, D, D);

    scores_kernel<<<dim3(S / 64, S / 64, B * H), 256>>>(Qp, Kp, attnbuf);
    softmax_kernel<<<B * H * S, 128>>>(attnbuf);
    ctx_kernel<<<dim3(S / 64, B * H), 256>>>(attnbuf, Vp, ctxp);

    gemm_nt_kernel<<<gemm_grid, 256>>>(ctxp, wo, bo, query, xp, M, D, D);
    ln_kernel<<<M, 256>>>(xp, gamma, beta, y);
}

// round 3
// speedup vs baseline: 1.5422x; 1.5422x over previous
#include <cuda_runtime.h>
#include <cstdint>
#include <math.h>

// Problem constants
static constexpr int B  = 8;
static constexpr int S  = 1024;
static constexpr int D  = 1024;
static constexpr int H  = 16;
static constexpr int DK = 64;
static constexpr int M  = B * S;        // 8192 rows for dense GEMMs

static constexpr size_t YSIZE    = (size_t)B * S * D;         // 8,388,608
static constexpr size_t ATTNSIZE = (size_t)B * H * S * S;     // 134,217,728

// Scratch
__device__ float g_Q[YSIZE];
__device__ float g_K[YSIZE];
__device__ float g_V[YSIZE];
__device__ float g_ctx[YSIZE];
__device__ float g_x[YSIZE];
__device__ float g_attn[ATTNSIZE];

__device__ __forceinline__ uint32_t f32_to_tf32_rn(float x) {
    uint32_t r;
    asm("cvt.rna.tf32.f32 %0, %1;" : "=r"(r) : "f"(x));
    return r;
}

__device__ __forceinline__ void mma_tf32(float c[4], const uint32_t a[4], const uint32_t b[2]) {
    asm volatile(
        "mma.sync.aligned.m16n8k8.row.col.f32.tf32.tf32.f32 "
        "{%0,%1,%2,%3}, {%4,%5,%6,%7}, {%8,%9}, {%0,%1,%2,%3};"
        : "+f"(c[0]), "+f"(c[1]), "+f"(c[2]), "+f"(c[3])
        : "r"(a[0]), "r"(a[1]), "r"(a[2]), "r"(a[3]), "r"(b[0]), "r"(b[1]));
}

// ===========================================================================
// Dense GEMM via warp-level tf32 MMA:
//   C[M,N] = A[M,K] @ W[N,K]^T + bias[N] (+ res[M,N])
// Block tile 128x128, BK=16, 256 threads = 8 warps (2m x 4n), warp tile 64x32.
// Register-staged prefetch: LDG -> cvt tf32 -> STS.
// ===========================================================================
static constexpr int BKg  = 16;
static constexpr int BPAD = 4;    // row pad (words) -> conflict-free frag reads

__global__ void __launch_bounds__(256, 2) gemm_tf32_mma(
    const float* __restrict__ A, const float* __restrict__ W,
    const float* __restrict__ bias, const float* __restrict__ res,
    float* __restrict__ C, int Kk, int Nn)
{
    __shared__ uint32_t As[128][BKg + BPAD];
    __shared__ uint32_t Ws[128][BKg + BPAD];

    const int tid  = threadIdx.x;
    const int wid  = tid >> 5;
    const int lane = tid & 31;
    const int warp_m = wid >> 2;          // 0..1
    const int warp_n = wid & 3;           // 0..3
    const int gID = lane >> 2;            // 0..7
    const int tig = lane & 3;             // 0..3

    const int bm = blockIdx.y * 128;
    const int bn = blockIdx.x * 128;

    // Staging: thread t loads A rows (t>>2, t>>2+64), k-chunk (t&3)*4
    const int srow = tid >> 2;            // 0..63
    const int skc  = (tid & 3) * 4;       // 0,4,8,12

    const float* Ag0 = A + (size_t)(bm + srow) * Kk + skc;
    const float* Ag1 = Ag0 + (size_t)64 * Kk;
    const float* Wg0 = W + (size_t)(bn + srow) * Kk + skc;
    const float* Wg1 = Wg0 + (size_t)64 * Kk;

    float acc[4][4][4];
#pragma unroll
    for (int i = 0; i < 4; i++)
#pragma unroll
        for (int j = 0; j < 4; j++)
#pragma unroll
            for (int r = 0; r < 4; r++) acc[i][j][r] = 0.f;

    const int NCH = Kk / BKg;

    float4 ra0 = *(const float4*)Ag0;
    float4 ra1 = *(const float4*)Ag1;
    float4 rw0 = *(const float4*)Wg0;
    float4 rw1 = *(const float4*)Wg1;

    for (int c = 0; c < NCH; c++) {
        // cvt + store staged tile
        {
            uint32_t v0 = f32_to_tf32_rn(ra0.x), v1 = f32_to_tf32_rn(ra0.y),
                     v2 = f32_to_tf32_rn(ra0.z), v3 = f32_to_tf32_rn(ra0.w);
            *(uint4*)&As[srow][skc] = make_uint4(v0, v1, v2, v3);
            v0 = f32_to_tf32_rn(ra1.x); v1 = f32_to_tf32_rn(ra1.y);
            v2 = f32_to_tf32_rn(ra1.z); v3 = f32_to_tf32_rn(ra1.w);
            *(uint4*)&As[srow + 64][skc] = make_uint4(v0, v1, v2, v3);
            v0 = f32_to_tf32_rn(rw0.x); v1 = f32_to_tf32_rn(rw0.y);
            v2 = f32_to_tf32_rn(rw0.z); v3 = f32_to_tf32_rn(rw0.w);
            *(uint4*)&Ws[srow][skc] = make_uint4(v0, v1, v2, v3);
            v0 = f32_to_tf32_rn(rw1.x); v1 = f32_to_tf32_rn(rw1.y);
            v2 = f32_to_tf32_rn(rw1.z); v3 = f32_to_tf32_rn(rw1.w);
            *(uint4*)&Ws[srow + 64][skc] = make_uint4(v0, v1, v2, v3);
        }
        __syncthreads();

        // prefetch next
        if (c + 1 < NCH) {
            Ag0 += BKg; Ag1 += BKg; Wg0 += BKg; Wg1 += BKg;
            ra0 = *(const float4*)Ag0;
            ra1 = *(const float4*)Ag1;
            rw0 = *(const float4*)Wg0;
            rw1 = *(const float4*)Wg1;
        }

        // compute: 2 k-steps of 8
#pragma unroll
        for (int kk = 0; kk < BKg; kk += 8) {
            uint32_t af[4][4];
            uint32_t bf[4][2];
#pragma unroll
            for (int mi = 0; mi < 4; mi++) {
                const int mr = warp_m * 64 + mi * 16 + gID;
                af[mi][0] = As[mr][kk + tig];
                af[mi][1] = As[mr + 8][kk + tig];
                af[mi][2] = As[mr][kk + tig + 4];
                af[mi][3] = As[mr + 8][kk + tig + 4];
            }
#pragma unroll
            for (int nj = 0; nj < 4; nj++) {
                const int nr = warp_n * 32 + nj * 8 + gID;
                bf[nj][0] = Ws[nr][kk + tig];
                bf[nj][1] = Ws[nr][kk + tig + 4];
            }
#pragma unroll
            for (int mi = 0; mi < 4; mi++)
#pragma unroll
                for (int nj = 0; nj < 4; nj++)
                    mma_tf32(acc[mi][nj], af[mi], bf[nj]);
        }
        __syncthreads();
    }

    // Epilogue
    const bool has_res = (res != nullptr);
#pragma unroll
    for (int mi = 0; mi < 4; mi++) {
        const int r0 = bm + warp_m * 64 + mi * 16 + gID;
#pragma unroll
        for (int nj = 0; nj < 4; nj++) {
            const int c0 = bn + warp_n * 32 + nj * 8 + tig * 2;
            const float b0 = bias[c0], b1 = bias[c0 + 1];
            float2 o0 = make_float2(acc[mi][nj][0] + b0, acc[mi][nj][1] + b1);
            float2 o1 = make_float2(acc[mi][nj][2] + b0, acc[mi][nj][3] + b1);
            const size_t i0 = (size_t)r0 * Nn + c0;
            const size_t i1 = (size_t)(r0 + 8) * Nn + c0;
            if (has_res) {
                float2 rv0 = *(const float2*)&res[i0];
                float2 rv1 = *(const float2*)&res[i1];
                o0.x += rv0.x; o0.y += rv0.y;
                o1.x += rv1.x; o1.y += rv1.y;
            }
            *(float2*)&C[i0] = o0;
            *(float2*)&C[i1] = o1;
        }
    }
}

// ---------------------------------------------------------------------------
// Scores: scores[bh, q, k] = (Q_head[q,:] . K_head[k,:]) / 8, masked (-1e9)
// ---------------------------------------------------------------------------
__global__ __launch_bounds__(256) void scores_kernel(
    const float* __restrict__ Q, const float* __restrict__ Kp,
    float* __restrict__ attnbuf)
{
    const int kt = blockIdx.x;
    const int qt = blockIdx.y;
    if (kt > qt) return;
    const int bh = blockIdx.z;
    const int b = bh / H, h = bh % H;

    __shared__ float Qs[64][65];
    __shared__ float Ks[64][65];

    const float* Qbase = Q + (size_t)b * S * D + h * DK;
    const float* Kbase = Kp + (size_t)b * S * D + h * DK;
    const int q0 = qt * 64, k0 = kt * 64;
    const int tid = threadIdx.x;

#pragma unroll
    for (int i = 0; i < 4; i++) {
        int idx = tid + i * 256;
        int r = idx >> 4;
        int c4 = idx & 15;
        float4 v = *(const float4*)&Qbase[(size_t)(q0 + r) * D + c4 * 4];
        Qs[r][c4 * 4 + 0] = v.x; Qs[r][c4 * 4 + 1] = v.y;
        Qs[r][c4 * 4 + 2] = v.z; Qs[r][c4 * 4 + 3] = v.w;
        float4 w = *(const float4*)&Kbase[(size_t)(k0 + r) * D + c4 * 4];
        Ks[r][c4 * 4 + 0] = w.x; Ks[r][c4 * 4 + 1] = w.y;
        Ks[r][c4 * 4 + 2] = w.z; Ks[r][c4 * 4 + 3] = w.w;
    }
    __syncthreads();

    const int tx = tid % 16, ty = tid / 16;
    float acc[4][4];
#pragma unroll
    for (int i = 0; i < 4; i++)
#pragma unroll
        for (int j = 0; j < 4; j++) acc[i][j] = 0.f;

#pragma unroll
    for (int k = 0; k < 64; k++) {
        float rq[4], rk[4];
#pragma unroll
        for (int i = 0; i < 4; i++) rq[i] = Qs[ty * 4 + i][k];
#pragma unroll
        for (int j = 0; j < 4; j++) rk[j] = Ks[tx * 4 + j][k];
#pragma unroll
        for (int i = 0; i < 4; i++)
#pragma unroll
            for (int j = 0; j < 4; j++) acc[i][j] = fmaf(rq[i], rk[j], acc[i][j]);
    }

    float* out = attnbuf + (size_t)bh * S * S;
#pragma unroll
    for (int i = 0; i < 4; i++) {
        int q = q0 + ty * 4 + i;
#pragma unroll
        for (int j = 0; j < 4; j++) {
            int kk = k0 + tx * 4 + j;
            float v = (kk <= q) ? acc[i][j] * 0.125f : -1e9f;
            out[(size_t)q * S + kk] = v;
        }
    }
}

// ---------------------------------------------------------------------------
// Single-pass causal softmax: one block per row; masked cols synthesized.
// ---------------------------------------------------------------------------
__global__ __launch_bounds__(256) void softmax_kernel(float* __restrict__ attnbuf)
{
    const size_t row = blockIdx.x;
    const int q = (int)(row & (S - 1));
    float* ptr = attnbuf + row * (size_t)S;
    const int tid = threadIdx.x;

    __shared__ float red[256];

    float v[4];
#pragma unroll
    for (int i = 0; i < 4; i++) {
        int col = tid + i * 256;
        v[i] = (col <= q) ? ptr[col] : -1e9f;
    }

    float m = fmaxf(fmaxf(v[0], v[1]), fmaxf(v[2], v[3]));
    red[tid] = m;
    __syncthreads();
#pragma unroll
    for (int s = 128; s > 0; s >>= 1) {
        if (tid < s) red[tid] = fmaxf(red[tid], red[tid + s]);
        __syncthreads();
    }
    m = red[0];
    __syncthreads();

    float e[4];
    float sum = 0.f;
#pragma unroll
    for (int i = 0; i < 4; i++) {
        e[i] = __expf(v[i] - m);
        sum += e[i];
    }
    red[tid] = sum;
    __syncthreads();
#pragma unroll
    for (int s = 128; s > 0; s >>= 1) {
        if (tid < s) red[tid] += red[tid + s];
        __syncthreads();
    }
    const float inv = 1.f / red[0];
    __syncthreads();

#pragma unroll
    for (int i = 0; i < 4; i++) ptr[tid + i * 256] = e[i] * inv;
}

// ---------------------------------------------------------------------------
// ctx[b, q, h*DK+dk] = sum_k attn[bh,q,k] * V_head[k,dk]
// ---------------------------------------------------------------------------
__global__ __launch_bounds__(256) void ctx_kernel(
    const float* __restrict__ attnbuf, const float* __restrict__ V,
    float* __restrict__ ctx)
{
    const int qt = blockIdx.x;
    const int bh = blockIdx.y;
    const int b = bh / H, h = bh % H;

    __shared__ float As[64][65];
    __shared__ float Vs[64][65];

    const float* arow  = attnbuf + (size_t)bh * S * S;
    const float* Vbase = V + (size_t)b * S * D + h * DK;
    const int q0 = qt * 64;
    const int tid = threadIdx.x;
    const int tx = tid % 16, ty = tid / 16;

    float acc[4][4];
#pragma unroll
    for (int i = 0; i < 4; i++)
#pragma unroll
        for (int j = 0; j < 4; j++) acc[i][j] = 0.f;

    for (int kt = 0; kt <= qt; kt++) {
        const int k0 = kt * 64;
#pragma unroll
        for (int i = 0; i < 4; i++) {
            int idx = tid + i * 256;
            int r = idx >> 4;
            int c4 = idx & 15;
            float4 a = *(const float4*)&arow[(size_t)(q0 + r) * S + k0 + c4 * 4];
            As[r][c4 * 4 + 0] = a.x; As[r][c4 * 4 + 1] = a.y;
            As[r][c4 * 4 + 2] = a.z; As[r][c4 * 4 + 3] = a.w;
            float4 v = *(const float4*)&Vbase[(size_t)(k0 + r) * D + c4 * 4];
            Vs[r][c4 * 4 + 0] = v.x; Vs[r][c4 * 4 + 1] = v.y;
            Vs[r][c4 * 4 + 2] = v.z; Vs[r][c4 * 4 + 3] = v.w;
        }
        __syncthreads();

#pragma unroll
        for (int k = 0; k < 64; k++) {
            float ra[4], rv[4];
#pragma unroll
            for (int i = 0; i < 4; i++) ra[i] = As[ty * 4 + i][k];
#pragma unroll
            for (int j = 0; j < 4; j++) rv[j] = Vs[k][tx * 4 + j];
#pragma unroll
            for (int i = 0; i < 4; i++)
#pragma unroll
                for (int j = 0; j < 4; j++) acc[i][j] = fmaf(ra[i], rv[j], acc[i][j]);
        }
        __syncthreads();
    }

#pragma unroll
    for (int i = 0; i < 4; i++) {
        int q = q0 + ty * 4 + i;
#pragma unroll
        for (int j = 0; j < 4; j++) {
            int dk = tx * 4 + j;
            ctx[(size_t)(b * S + q) * D + h * DK + dk] = acc[i][j];
        }
    }
}

// ---------------------------------------------------------------------------
// Row LayerNorm
// ---------------------------------------------------------------------------
__global__ __launch_bounds__(256) void ln_kernel(
    const float* __restrict__ x, const float* __restrict__ gamma,
    const float* __restrict__ beta, float* __restrict__ y)
{
    const size_t row = blockIdx.x;
    const float* xr = x + row * (size_t)D;
    float* yr = y + row * (size_t)D;
    const int tid = threadIdx.x;

    __shared__ float rs[256], rs2[256];

    float s = 0.f, s2 = 0.f;
#pragma unroll
    for (int i = 0; i < 4; i++) {
        float v = xr[tid + i * 256];
        s += v;
        s2 += v * v;
    }
    rs[tid] = s; rs2[tid] = s2;
    __syncthreads();
#pragma unroll
    for (int k = 128; k > 0; k >>= 1) {
        if (tid < k) { rs[tid] += rs[tid + k]; rs2[tid] += rs2[tid + k]; }
        __syncthreads();
    }
    const float mean = rs[0] * (1.f / D);
    const float var  = rs2[0] * (1.f / D) - mean * mean;
    const float rstd = rsqrtf(var + 1e-5f);

#pragma unroll
    for (int i = 0; i < 4; i++) {
        int c = tid + i * 256;
        yr[c] = (xr[c] - mean) * rstd * gamma[c] + beta[c];
    }
}

// ---------------------------------------------------------------------------
// Launch
// ---------------------------------------------------------------------------
extern "C" void kernel_launch(void* const* d_in, const int* in_sizes, int n_in,
                              void* d_out, int out_size)
{
    const float* query = (const float*)d_in[0];
    const float* key   = (const float*)d_in[1];
    const float* value = (const float*)d_in[2];
    const float* wq = (const float*)d_in[4];
    const float* bq = (const float*)d_in[5];
    const float* wk = (const float*)d_in[6];
    const float* bk = (const float*)d_in[7];
    const float* wv = (const float*)d_in[8];
    const float* bv = (const float*)d_in[9];
    const float* wo = (const float*)d_in[10];
    const float* bo = (const float*)d_in[11];
    const float* gamma = (const float*)d_in[12];
    const float* beta  = (const float*)d_in[13];

    float* y = (float*)d_out;

    float *Qp, *Kp, *Vp, *ctxp, *xp, *attnp;
    cudaGetSymbolAddress((void**)&Qp,   g_Q);
    cudaGetSymbolAddress((void**)&Kp,   g_K);
    cudaGetSymbolAddress((void**)&Vp,   g_V);
    cudaGetSymbolAddress((void**)&ctxp, g_ctx);
    cudaGetSymbolAddress((void**)&xp,   g_x);
    cudaGetSymbolAddress((void**)&attnp, g_attn);

    float* attnbuf = ((size_t)out_size >= YSIZE + ATTNSIZE) ? (y + YSIZE) : attnp;

    const dim3 gg(D / 128, M / 128);   // (8, 64)
    gemm_tf32_mma<<<gg, 256>>>(query, wq, bq, nullptr, Qp, D, D);
    gemm_tf32_mma<<<gg, 256>>>(key,   wk, bk, nullptr, Kp, D, D);
    gemm_tf32_mma<<<gg, 256>>>(value, wv, bv, nullptr, Vp, D, D);

    scores_kernel<<<dim3(S / 64, S / 64, B * H), 256>>>(Qp, Kp, attnbuf);
    softmax_kernel<<<B * H * S, 256>>>(attnbuf);
    ctx_kernel<<<dim3(S / 64, B * H), 256>>>(attnbuf, Vp, ctxp);

    gemm_tf32_mma<<<gg, 256>>>(ctxp, wo, bo, query, xp, D, D);
    ln_kernel<<<M, 256>>>(xp, gamma, beta, y);
}

// round 4
// speedup vs baseline: 2.1729x; 1.4089x over previous
#include <cuda_runtime.h>
#include <cstdint>
#include <math.h>

// Problem constants
static constexpr int B  = 8;
static constexpr int S  = 1024;
static constexpr int D  = 1024;
static constexpr int H  = 16;
static constexpr int DK = 64;
static constexpr int M  = B * S;

static constexpr size_t YSIZE    = (size_t)B * S * D;
static constexpr size_t ATTNSIZE = (size_t)B * H * S * S;

// Scratch
__device__ float g_Q[YSIZE];
__device__ float g_K[YSIZE];
__device__ float g_V[YSIZE];
__device__ float g_ctx[YSIZE];
__device__ float g_x[YSIZE];
__device__ float g_attn[ATTNSIZE];

__device__ __forceinline__ uint32_t f32_to_tf32_rn(float x) {
    uint32_t r;
    asm("cvt.rna.tf32.f32 %0, %1;" : "=r"(r) : "f"(x));
    return r;
}

__device__ __forceinline__ void mma_tf32(float c[4], const uint32_t a[4], const uint32_t b[2]) {
    asm volatile(
        "mma.sync.aligned.m16n8k8.row.col.f32.tf32.tf32.f32 "
        "{%0,%1,%2,%3}, {%4,%5,%6,%7}, {%8,%9}, {%0,%1,%2,%3};"
        : "+f"(c[0]), "+f"(c[1]), "+f"(c[2]), "+f"(c[3])
        : "r"(a[0]), "r"(a[1]), "r"(a[2]), "r"(a[3]), "r"(b[0]), "r"(b[1]));
}

// ===========================================================================
// Dense GEMM via warp-level tf32 MMA (unchanged from R3):
//   C[M,N] = A[M,K] @ W[N,K]^T + bias[N] (+ res[M,N])
// ===========================================================================
static constexpr int BKg  = 16;
static constexpr int BPAD = 4;

__global__ void __launch_bounds__(256, 2) gemm_tf32_mma(
    const float* __restrict__ A, const float* __restrict__ W,
    const float* __restrict__ bias, const float* __restrict__ res,
    float* __restrict__ C, int Kk, int Nn)
{
    __shared__ uint32_t As[128][BKg + BPAD];
    __shared__ uint32_t Ws[128][BKg + BPAD];

    const int tid  = threadIdx.x;
    const int wid  = tid >> 5;
    const int lane = tid & 31;
    const int warp_m = wid >> 2;
    const int warp_n = wid & 3;
    const int gID = lane >> 2;
    const int tig = lane & 3;

    const int bm = blockIdx.y * 128;
    const int bn = blockIdx.x * 128;

    const int srow = tid >> 2;
    const int skc  = (tid & 3) * 4;

    const float* Ag0 = A + (size_t)(bm + srow) * Kk + skc;
    const float* Ag1 = Ag0 + (size_t)64 * Kk;
    const float* Wg0 = W + (size_t)(bn + srow) * Kk + skc;
    const float* Wg1 = Wg0 + (size_t)64 * Kk;

    float acc[4][4][4];
#pragma unroll
    for (int i = 0; i < 4; i++)
#pragma unroll
        for (int j = 0; j < 4; j++)
#pragma unroll
            for (int r = 0; r < 4; r++) acc[i][j][r] = 0.f;

    const int NCH = Kk / BKg;

    float4 ra0 = *(const float4*)Ag0;
    float4 ra1 = *(const float4*)Ag1;
    float4 rw0 = *(const float4*)Wg0;
    float4 rw1 = *(const float4*)Wg1;

    for (int c = 0; c < NCH; c++) {
        {
            uint32_t v0 = f32_to_tf32_rn(ra0.x), v1 = f32_to_tf32_rn(ra0.y),
                     v2 = f32_to_tf32_rn(ra0.z), v3 = f32_to_tf32_rn(ra0.w);
            *(uint4*)&As[srow][skc] = make_uint4(v0, v1, v2, v3);
            v0 = f32_to_tf32_rn(ra1.x); v1 = f32_to_tf32_rn(ra1.y);
            v2 = f32_to_tf32_rn(ra1.z); v3 = f32_to_tf32_rn(ra1.w);
            *(uint4*)&As[srow + 64][skc] = make_uint4(v0, v1, v2, v3);
            v0 = f32_to_tf32_rn(rw0.x); v1 = f32_to_tf32_rn(rw0.y);
            v2 = f32_to_tf32_rn(rw0.z); v3 = f32_to_tf32_rn(rw0.w);
            *(uint4*)&Ws[srow][skc] = make_uint4(v0, v1, v2, v3);
            v0 = f32_to_tf32_rn(rw1.x); v1 = f32_to_tf32_rn(rw1.y);
            v2 = f32_to_tf32_rn(rw1.z); v3 = f32_to_tf32_rn(rw1.w);
            *(uint4*)&Ws[srow + 64][skc] = make_uint4(v0, v1, v2, v3);
        }
        __syncthreads();

        if (c + 1 < NCH) {
            Ag0 += BKg; Ag1 += BKg; Wg0 += BKg; Wg1 += BKg;
            ra0 = *(const float4*)Ag0;
            ra1 = *(const float4*)Ag1;
            rw0 = *(const float4*)Wg0;
            rw1 = *(const float4*)Wg1;
        }

#pragma unroll
        for (int kk = 0; kk < BKg; kk += 8) {
            uint32_t af[4][4];
            uint32_t bf[4][2];
#pragma unroll
            for (int mi = 0; mi < 4; mi++) {
                const int mr = warp_m * 64 + mi * 16 + gID;
                af[mi][0] = As[mr][kk + tig];
                af[mi][1] = As[mr + 8][kk + tig];
                af[mi][2] = As[mr][kk + tig + 4];
                af[mi][3] = As[mr + 8][kk + tig + 4];
            }
#pragma unroll
            for (int nj = 0; nj < 4; nj++) {
                const int nr = warp_n * 32 + nj * 8 + gID;
                bf[nj][0] = Ws[nr][kk + tig];
                bf[nj][1] = Ws[nr][kk + tig + 4];
            }
#pragma unroll
            for (int mi = 0; mi < 4; mi++)
#pragma unroll
                for (int nj = 0; nj < 4; nj++)
                    mma_tf32(acc[mi][nj], af[mi], bf[nj]);
        }
        __syncthreads();
    }

    const bool has_res = (res != nullptr);
#pragma unroll
    for (int mi = 0; mi < 4; mi++) {
        const int r0 = bm + warp_m * 64 + mi * 16 + gID;
#pragma unroll
        for (int nj = 0; nj < 4; nj++) {
            const int c0 = bn + warp_n * 32 + nj * 8 + tig * 2;
            const float b0 = bias[c0], b1 = bias[c0 + 1];
            float2 o0 = make_float2(acc[mi][nj][0] + b0, acc[mi][nj][1] + b1);
            float2 o1 = make_float2(acc[mi][nj][2] + b0, acc[mi][nj][3] + b1);
            const size_t i0 = (size_t)r0 * Nn + c0;
            const size_t i1 = (size_t)(r0 + 8) * Nn + c0;
            if (has_res) {
                float2 rv0 = *(const float2*)&res[i0];
                float2 rv1 = *(const float2*)&res[i1];
                o0.x += rv0.x; o0.y += rv0.y;
                o1.x += rv1.x; o1.y += rv1.y;
            }
            *(float2*)&C[i0] = o0;
            *(float2*)&C[i1] = o1;
        }
    }
}

// ===========================================================================
// Scores via tf32 MMA: S[q,k] = Q_head[q,:] . K_head[k,:] * 0.125
// Tile 128x128, DK=64 fully staged. No masking (softmax never reads k>q).
// Upper-triangular tiles skipped.
// Smem pitch 68 words -> fragment bank = 4*gID + tig: conflict-free.
// ===========================================================================
static constexpr int SC_PITCH = 68;
static constexpr int SC_SMEM  = 2 * 128 * SC_PITCH * 4;   // 69632 bytes

__global__ void __launch_bounds__(256, 1) scores_mma(
    const float* __restrict__ Q, const float* __restrict__ Kp,
    float* __restrict__ attnbuf)
{
    extern __shared__ uint32_t sm[];
    uint32_t (*Qs)[SC_PITCH] = (uint32_t(*)[SC_PITCH])sm;
    uint32_t (*Ks)[SC_PITCH] = (uint32_t(*)[SC_PITCH])(sm + 128 * SC_PITCH);

    const int kt = blockIdx.x;
    const int qt = blockIdx.y;
    if (kt > qt) return;
    const int bh = blockIdx.z;
    const int b = bh >> 4, h = bh & 15;

    const int q0 = qt * 128, k0 = kt * 128;
    const float* Qbase = Q + (size_t)b * S * D + h * DK;
    const float* Kbase = Kp + (size_t)b * S * D + h * DK;

    const int tid = threadIdx.x;

    // Stage Q,K tiles: 128 rows x 64 cols each = 2048 float4 per operand
#pragma unroll
    for (int i = 0; i < 8; i++) {
        const int f = tid + i * 256;
        const int r = f >> 4, c4 = f & 15;
        float4 v = *(const float4*)&Qbase[(size_t)(q0 + r) * D + c4 * 4];
        *(uint4*)&Qs[r][c4 * 4] = make_uint4(
            f32_to_tf32_rn(v.x), f32_to_tf32_rn(v.y),
            f32_to_tf32_rn(v.z), f32_to_tf32_rn(v.w));
        float4 w = *(const float4*)&Kbase[(size_t)(k0 + r) * D + c4 * 4];
        *(uint4*)&Ks[r][c4 * 4] = make_uint4(
            f32_to_tf32_rn(w.x), f32_to_tf32_rn(w.y),
            f32_to_tf32_rn(w.z), f32_to_tf32_rn(w.w));
    }
    __syncthreads();

    const int wid  = tid >> 5;
    const int lane = tid & 31;
    const int warp_m = wid >> 2;    // 0..1
    const int warp_n = wid & 3;     // 0..3
    const int gID = lane >> 2;
    const int tig = lane & 3;

    float acc[4][4][4];
#pragma unroll
    for (int i = 0; i < 4; i++)
#pragma unroll
        for (int j = 0; j < 4; j++)
#pragma unroll
            for (int r = 0; r < 4; r++) acc[i][j][r] = 0.f;

#pragma unroll
    for (int kk = 0; kk < 64; kk += 8) {
        uint32_t af[4][4];
        uint32_t bf[4][2];
#pragma unroll
        for (int mi = 0; mi < 4; mi++) {
            const int mr = warp_m * 64 + mi * 16 + gID;
            af[mi][0] = Qs[mr][kk + tig];
            af[mi][1] = Qs[mr + 8][kk + tig];
            af[mi][2] = Qs[mr][kk + tig + 4];
            af[mi][3] = Qs[mr + 8][kk + tig + 4];
        }
#pragma unroll
        for (int nj = 0; nj < 4; nj++) {
            const int nr = warp_n * 32 + nj * 8 + gID;
            bf[nj][0] = Ks[nr][kk + tig];
            bf[nj][1] = Ks[nr][kk + tig + 4];
        }
#pragma unroll
        for (int mi = 0; mi < 4; mi++)
#pragma unroll
            for (int nj = 0; nj < 4; nj++)
                mma_tf32(acc[mi][nj], af[mi], bf[nj]);
    }

    float* out = attnbuf + (size_t)bh * S * S;
#pragma unroll
    for (int mi = 0; mi < 4; mi++) {
        const int r0 = q0 + warp_m * 64 + mi * 16 + gID;
#pragma unroll
        for (int nj = 0; nj < 4; nj++) {
            const int c0 = k0 + warp_n * 32 + nj * 8 + tig * 2;
            *(float2*)&out[(size_t)r0 * S + c0] =
                make_float2(acc[mi][nj][0] * 0.125f, acc[mi][nj][1] * 0.125f);
            *(float2*)&out[(size_t)(r0 + 8) * S + c0] =
                make_float2(acc[mi][nj][2] * 0.125f, acc[mi][nj][3] * 0.125f);
        }
    }
}

// ---------------------------------------------------------------------------
// Single-pass causal softmax (unchanged).
// ---------------------------------------------------------------------------
__global__ __launch_bounds__(256) void softmax_kernel(float* __restrict__ attnbuf)
{
    const size_t row = blockIdx.x;
    const int q = (int)(row & (S - 1));
    float* ptr = attnbuf + row * (size_t)S;
    const int tid = threadIdx.x;

    __shared__ float red[256];

    float v[4];
#pragma unroll
    for (int i = 0; i < 4; i++) {
        int col = tid + i * 256;
        v[i] = (col <= q) ? ptr[col] : -1e9f;
    }

    float m = fmaxf(fmaxf(v[0], v[1]), fmaxf(v[2], v[3]));
    red[tid] = m;
    __syncthreads();
#pragma unroll
    for (int s = 128; s > 0; s >>= 1) {
        if (tid < s) red[tid] = fmaxf(red[tid], red[tid + s]);
        __syncthreads();
    }
    m = red[0];
    __syncthreads();

    float e[4];
    float sum = 0.f;
#pragma unroll
    for (int i = 0; i < 4; i++) {
        e[i] = __expf(v[i] - m);
        sum += e[i];
    }
    red[tid] = sum;
    __syncthreads();
#pragma unroll
    for (int s = 128; s > 0; s >>= 1) {
        if (tid < s) red[tid] += red[tid + s];
        __syncthreads();
    }
    const float inv = 1.f / red[0];
    __syncthreads();

#pragma unroll
    for (int i = 0; i < 4; i++) ptr[tid + i * 256] = e[i] * inv;
}

// ===========================================================================
// ctx via tf32 MMA: ctx[q, dk] = sum_k attn[q,k] * V_head[k,dk]
// Tile 128q x 64dk per block, k-chunks of 32, chunks limited by causality.
// attn staged row-major pitch 36; V staged k-major pitch 72 (transposed reads
// bank = 8*tig + gID: conflict-free).
// ===========================================================================
__global__ void __launch_bounds__(256, 2) ctx_mma(
    const float* __restrict__ attnbuf, const float* __restrict__ V,
    float* __restrict__ ctx)
{
    __shared__ uint32_t As[128][36];
    __shared__ uint32_t Vs[32][72];

    const int qt = blockIdx.x;
    const int bh = blockIdx.y;
    const int b = bh >> 4, h = bh & 15;

    const int q0 = qt * 128;
    const float* arow  = attnbuf + (size_t)bh * S * S;
    const float* Vbase = V + (size_t)b * S * D + h * DK;
    const int tid = threadIdx.x;

    const int wid  = tid >> 5;
    const int lane = tid & 31;
    const int warp_m = wid >> 2;    // 0..1
    const int warp_n = wid & 3;     // 0..3
    const int gID = lane >> 2;
    const int tig = lane & 3;

    // staging maps
    const int ar = tid >> 3;           // attn row step base (with +32*i)
    const int ac4 = tid & 7;           // attn col float4 (0..7)
    const int vr = tid >> 4;           // V k-row (0..15, +16)
    const int vc4 = tid & 15;          // V dk float4 (0..15)

    float acc[4][2][4];
#pragma unroll
    for (int i = 0; i < 4; i++)
#pragma unroll
        for (int j = 0; j < 2; j++)
#pragma unroll
            for (int r = 0; r < 4; r++) acc[i][j][r] = 0.f;

    const int NCH = qt * 4 + 4;

    // prefetch chunk 0
    float4 pa[4], pv[2];
#pragma unroll
    for (int i = 0; i < 4; i++)
        pa[i] = *(const float4*)&arow[(size_t)(q0 + ar + i * 32) * S + ac4 * 4];
#pragma unroll
    for (int i = 0; i < 2; i++)
        pv[i] = *(const float4*)&Vbase[(size_t)(vr + i * 16) * D + vc4 * 4];

    for (int c = 0; c < NCH; c++) {
#pragma unroll
        for (int i = 0; i < 4; i++) {
            *(uint4*)&As[ar + i * 32][ac4 * 4] = make_uint4(
                f32_to_tf32_rn(pa[i].x), f32_to_tf32_rn(pa[i].y),
                f32_to_tf32_rn(pa[i].z), f32_to_tf32_rn(pa[i].w));
        }
#pragma unroll
        for (int i = 0; i < 2; i++) {
            *(uint4*)&Vs[vr + i * 16][vc4 * 4] = make_uint4(
                f32_to_tf32_rn(pv[i].x), f32_to_tf32_rn(pv[i].y),
                f32_to_tf32_rn(pv[i].z), f32_to_tf32_rn(pv[i].w));
        }
        __syncthreads();

        if (c + 1 < NCH) {
            const int kc = (c + 1) * 32;
#pragma unroll
            for (int i = 0; i < 4; i++)
                pa[i] = *(const float4*)&arow[(size_t)(q0 + ar + i * 32) * S + kc + ac4 * 4];
#pragma unroll
            for (int i = 0; i < 2; i++)
                pv[i] = *(const float4*)&Vbase[(size_t)(kc + vr + i * 16) * D + vc4 * 4];
        }

#pragma unroll
        for (int kk = 0; kk < 32; kk += 8) {
            uint32_t af[4][4];
            uint32_t bf[2][2];
#pragma unroll
            for (int mi = 0; mi < 4; mi++) {
                const int mr = warp_m * 64 + mi * 16 + gID;
                af[mi][0] = As[mr][kk + tig];
                af[mi][1] = As[mr + 8][kk + tig];
                af[mi][2] = As[mr][kk + tig + 4];
                af[mi][3] = As[mr + 8][kk + tig + 4];
            }
#pragma unroll
            for (int nj = 0; nj < 2; nj++) {
                const int nr = warp_n * 16 + nj * 8 + gID;
                bf[nj][0] = Vs[kk + tig][nr];      // transposed read
                bf[nj][1] = Vs[kk + tig + 4][nr];
            }
#pragma unroll
            for (int mi = 0; mi < 4; mi++)
#pragma unroll
                for (int nj = 0; nj < 2; nj++)
                    mma_tf32(acc[mi][nj], af[mi], bf[nj]);
        }
        __syncthreads();
    }

    // Epilogue: ctx[(b*S+q)*D + h*64 + col]
#pragma unroll
    for (int mi = 0; mi < 4; mi++) {
        const int q = q0 + warp_m * 64 + mi * 16 + gID;
#pragma unroll
        for (int nj = 0; nj < 2; nj++) {
            const int c0 = warp_n * 16 + nj * 8 + tig * 2;
            const size_t i0 = (size_t)(b * S + q) * D + h * DK + c0;
            const size_t i1 = (size_t)(b * S + q + 8) * D + h * DK + c0;
            *(float2*)&ctx[i0] = make_float2(acc[mi][nj][0], acc[mi][nj][1]);
            *(float2*)&ctx[i1] = make_float2(acc[mi][nj][2], acc[mi][nj][3]);
        }
    }
}

// ---------------------------------------------------------------------------
// Row LayerNorm (unchanged)
// ---------------------------------------------------------------------------
__global__ __launch_bounds__(256) void ln_kernel(
    const float* __restrict__ x, const float* __restrict__ gamma,
    const float* __restrict__ beta, float* __restrict__ y)
{
    const size_t row = blockIdx.x;
    const float* xr = x + row * (size_t)D;
    float* yr = y + row * (size_t)D;
    const int tid = threadIdx.x;

    __shared__ float rs[256], rs2[256];

    float s = 0.f, s2 = 0.f;
#pragma unroll
    for (int i = 0; i < 4; i++) {
        float v = xr[tid + i * 256];
        s += v;
        s2 += v * v;
    }
    rs[tid] = s; rs2[tid] = s2;
    __syncthreads();
#pragma unroll
    for (int k = 128; k > 0; k >>= 1) {
        if (tid < k) { rs[tid] += rs[tid + k]; rs2[tid] += rs2[tid + k]; }
        __syncthreads();
    }
    const float mean = rs[0] * (1.f / D);
    const float var  = rs2[0] * (1.f / D) - mean * mean;
    const float rstd = rsqrtf(var + 1e-5f);

#pragma unroll
    for (int i = 0; i < 4; i++) {
        int c = tid + i * 256;
        yr[c] = (xr[c] - mean) * rstd * gamma[c] + beta[c];
    }
}

// ---------------------------------------------------------------------------
// Launch
// ---------------------------------------------------------------------------
extern "C" void kernel_launch(void* const* d_in, const int* in_sizes, int n_in,
                              void* d_out, int out_size)
{
    const float* query = (const float*)d_in[0];
    const float* key   = (const float*)d_in[1];
    const float* value = (const float*)d_in[2];
    const float* wq = (const float*)d_in[4];
    const float* bq = (const float*)d_in[5];
    const float* wk = (const float*)d_in[6];
    const float* bk = (const float*)d_in[7];
    const float* wv = (const float*)d_in[8];
    const float* bv = (const float*)d_in[9];
    const float* wo = (const float*)d_in[10];
    const float* bo = (const float*)d_in[11];
    const float* gamma = (const float*)d_in[12];
    const float* beta  = (const float*)d_in[13];

    float* y = (float*)d_out;

    float *Qp, *Kp, *Vp, *ctxp, *xp, *attnp;
    cudaGetSymbolAddress((void**)&Qp,   g_Q);
    cudaGetSymbolAddress((void**)&Kp,   g_K);
    cudaGetSymbolAddress((void**)&Vp,   g_V);
    cudaGetSymbolAddress((void**)&ctxp, g_ctx);
    cudaGetSymbolAddress((void**)&xp,   g_x);
    cudaGetSymbolAddress((void**)&attnp, g_attn);

    float* attnbuf = ((size_t)out_size >= YSIZE + ATTNSIZE) ? (y + YSIZE) : attnp;

    cudaFuncSetAttribute(scores_mma,
                         cudaFuncAttributeMaxDynamicSharedMemorySize, SC_SMEM);

    const dim3 gg(D / 128, M / 128);   // (8, 64)
    gemm_tf32_mma<<<gg, 256>>>(query, wq, bq, nullptr, Qp, D, D);
    gemm_tf32_mma<<<gg, 256>>>(key,   wk, bk, nullptr, Kp, D, D);
    gemm_tf32_mma<<<gg, 256>>>(value, wv, bv, nullptr, Vp, D, D);

    scores_mma<<<dim3(S / 128, S / 128, B * H), 256, SC_SMEM>>>(Qp, Kp, attnbuf);
    softmax_kernel<<<B * H * S, 256>>>(attnbuf);
    ctx_mma<<<dim3(S / 128, B * H), 256>>>(attnbuf, Vp, ctxp);

    gemm_tf32_mma<<<gg, 256>>>(ctxp, wo, bo, query, xp, D, D);
    ln_kernel<<<M, 256>>>(xp, gamma, beta, y);
}